// round 5
// baseline (speedup 1.0000x reference)
#include <cuda_runtime.h>
#include <math.h>

#define NB      2048
#define NENT    8256
#define KAPPA   0.276f

#define LSTRIDE 132   // long-row stride (f2), == 4 mod 16, even
#define SSTRIDE 68    // short-row stride (f2), == 4 mod 16, even

__device__ float g_rn[NB];

__device__ __forceinline__ float2 cmul(float2 a, float2 b) {
    return make_float2(a.x * b.x - a.y * b.y, a.x * b.y + a.y * b.x);
}
__device__ __forceinline__ float2 cadd(float2 a, float2 b) {
    return make_float2(a.x + b.x, a.y + b.y);
}
__device__ __forceinline__ float2 csub(float2 a, float2 b) {
    return make_float2(a.x - b.x, a.y - b.y);
}
__device__ __forceinline__ float2 cdiv(float2 a, float2 b) {
    float inv = 1.0f / (b.x * b.x + b.y * b.y);
    return make_float2((a.x * b.x + a.y * b.y) * inv,
                       (a.y * b.x - a.x * b.y) * inv);
}

// ---------- w = L * v : long row from REGISTERS, short row from smem ----------
// Thread (warp,g,q): p = 8w+g. Long row 127-p cached in Lr4[16] (cols 2(q+4k), 2(q+4k)+1).
// Unconditional 16-iter loop (zero-padded smem -> zero regs beyond row end).
// Short row p read from smem, sharing the same v4 load.
__device__ __forceinline__ void matvecW(float2* __restrict__ wout,
                                        const float2* __restrict__ vin,
                                        const float2* __restrict__ Lshort,
                                        const float4* __restrict__ Lr4,
                                        int p, int q) {
    const float4* v4  = reinterpret_cast<const float4*>(vin);
    const float4* Ls4 = reinterpret_cast<const float4*>(Lshort + p * SSTRIDE);
    float4 as4 = make_float4(0.f, 0.f, 0.f, 0.f);
    float4 ar4 = make_float4(0.f, 0.f, 0.f, 0.f);
    #pragma unroll
    for (int k = 0; k < 16; k++) {
        int j = q + 4 * k;           // f4 index; covers cols 2j, 2j+1
        float4 vf = v4[j];
        float4 lf = Lr4[k];          // registers!
        as4.x = fmaf(lf.x, vf.x, fmaf(-lf.y, vf.y, as4.x));
        as4.y = fmaf(lf.x, vf.y, fmaf( lf.y, vf.x, as4.y));
        as4.z = fmaf(lf.z, vf.z, fmaf(-lf.w, vf.w, as4.z));
        as4.w = fmaf(lf.z, vf.w, fmaf( lf.w, vf.z, as4.w));
        if (2 * j <= p) {            // short row (zeros pad the odd edge)
            float4 ls = Ls4[j];
            ar4.x = fmaf(ls.x, vf.x, fmaf(-ls.y, vf.y, ar4.x));
            ar4.y = fmaf(ls.x, vf.y, fmaf( ls.y, vf.x, ar4.y));
            ar4.z = fmaf(ls.z, vf.z, fmaf(-ls.w, vf.w, ar4.z));
            ar4.w = fmaf(ls.z, vf.w, fmaf( ls.w, vf.z, ar4.w));
        }
    }
    float2 as = make_float2(as4.x + as4.z, as4.y + as4.w);
    float2 ar = make_float2(ar4.x + ar4.z, ar4.y + ar4.w);
    #pragma unroll
    for (int o = 1; o <= 2; o <<= 1) {
        ar.x += __shfl_xor_sync(0xffffffffu, ar.x, o);
        ar.y += __shfl_xor_sync(0xffffffffu, ar.y, o);
        as.x += __shfl_xor_sync(0xffffffffu, as.x, o);
        as.y += __shfl_xor_sync(0xffffffffu, as.y, o);
    }
    if (q == 0) { wout[p] = ar; wout[127 - p] = as; }
}

// ---------- u = L^H * w : from smem (column access), constant strides ----------
__device__ __forceinline__ void matvecU(float2* __restrict__ uout,
                                        const float2* __restrict__ win,
                                        const float2* __restrict__ Lshort,
                                        const float2* __restrict__ Llong,
                                        int c, int q) {
    int c2 = 127 - c;
    float2 ac = make_float2(0.f, 0.f), ac2 = make_float2(0.f, 0.f);
    {   // long rows: p = q + 4k, k = 0..15
        const float2* Lp = Llong + q * LSTRIDE;
        #pragma unroll 4
        for (int k = 0; k < 16; k++) {
            float2 wl = win[127 - (q + 4 * k)];
            float2 l = Lp[c];
            ac.x = fmaf(l.x, wl.x, fmaf( l.y, wl.y, ac.x));
            ac.y = fmaf(l.x, wl.y, fmaf(-l.y, wl.x, ac.y));
            Lp += 4 * LSTRIDE;
        }
    }
    {   // complement column c2: long rows p = q..c step 4
        const float2* Lp = Llong + q * LSTRIDE + c2;
        #pragma unroll 4
        for (int p = q; p <= c; p += 4) {
            float2 wl = win[127 - p];
            float2 l = *Lp;
            ac2.x = fmaf(l.x, wl.x, fmaf( l.y, wl.y, ac2.x));
            ac2.y = fmaf(l.x, wl.y, fmaf(-l.y, wl.x, ac2.y));
            Lp += 4 * LSTRIDE;
        }
    }
    {   // short rows: r = c+q .. 63 step 4
        const float2* Sp = Lshort + (c + q) * SSTRIDE + c;
        #pragma unroll 4
        for (int r = c + q; r <= 63; r += 4) {
            float2 ws = win[r];
            float2 l = *Sp;
            ac.x = fmaf(l.x, ws.x, fmaf( l.y, ws.y, ac.x));
            ac.y = fmaf(l.x, ws.y, fmaf(-l.y, ws.x, ac.y));
            Sp += 4 * SSTRIDE;
        }
    }
    #pragma unroll
    for (int o = 1; o <= 2; o <<= 1) {
        ac.x  += __shfl_xor_sync(0xffffffffu, ac.x,  o);
        ac.y  += __shfl_xor_sync(0xffffffffu, ac.y,  o);
        ac2.x += __shfl_xor_sync(0xffffffffu, ac2.x, o);
        ac2.y += __shfl_xor_sync(0xffffffffu, ac2.y, o);
    }
    if (q == 0) { uout[c] = ac; uout[c2] = ac2; }
}

// ---------- Wilson-Dirac stencil: g=+1 -> D, g=-1 -> Ddag ----------
__device__ __forceinline__ void dirac(float2* __restrict__ out,
                                      const float2* __restrict__ in,
                                      const float2* __restrict__ Us,
                                      float g) {
    int t = threadIdx.x;
    if (t < 64) {
        int x = t >> 3, y = t & 7;
        float2 a0 = in[2 * t], a1 = in[2 * t + 1];
        float2 s0 = make_float2(0.f, 0.f), s1 = make_float2(0.f, 0.f);
        {   // mu = 0, G = sigma_x
            int sp = (((x + 1) & 7) << 3) | y;
            int sm = (((x + 7) & 7) << 3) | y;
            float2 u  = Us[t];
            float2 ub = Us[sm]; ub.y = -ub.y;
            float2 f0 = cmul(u,  in[2 * sp]), f1 = cmul(u,  in[2 * sp + 1]);
            float2 b0 = cmul(ub, in[2 * sm]), b1 = cmul(ub, in[2 * sm + 1]);
            s0.x += f0.x - g * f1.x + b0.x + g * b1.x;
            s0.y += f0.y - g * f1.y + b0.y + g * b1.y;
            s1.x += f1.x - g * f0.x + b1.x + g * b0.x;
            s1.y += f1.y - g * f0.y + b1.y + g * b0.y;
        }
        {   // mu = 1, G = sigma_y
            int sp = (x << 3) | ((y + 1) & 7);
            int sm = (x << 3) | ((y + 7) & 7);
            float2 u  = Us[64 + t];
            float2 ub = Us[64 + sm]; ub.y = -ub.y;
            float2 f0 = cmul(u,  in[2 * sp]), f1 = cmul(u,  in[2 * sp + 1]);
            float2 b0 = cmul(ub, in[2 * sm]), b1 = cmul(ub, in[2 * sm + 1]);
            s0.x += f0.x - g * f1.y + b0.x + g * b1.y;
            s0.y += f0.y + g * f1.x + b0.y - g * b1.x;
            s1.x += f1.x + g * f0.y + b1.x - g * b0.y;
            s1.y += f1.y - g * f0.x + b1.y + g * b0.x;
        }
        out[2 * t]     = make_float2(a0.x - KAPPA * s0.x, a0.y - KAPPA * s0.y);
        out[2 * t + 1] = make_float2(a1.x - KAPPA * s1.x, a1.y - KAPPA * s1.y);
    }
}

// ---------- block-wide complex dot (rotating red bank; no trailing sync) ----------
__device__ __forceinline__ float2 dot_all(const float2* __restrict__ a,
                                          const float2* __restrict__ c,
                                          float2* __restrict__ red, int off) {
    int tid = threadIdx.x;
    float2 s = make_float2(0.f, 0.f);
    if (tid < 128) {
        float2 av = a[tid], cv = c[tid];
        s.x = av.x * cv.x + av.y * cv.y;
        s.y = av.x * cv.y - av.y * cv.x;
    }
    #pragma unroll
    for (int o = 16; o; o >>= 1) {
        s.x += __shfl_down_sync(0xffffffffu, s.x, o);
        s.y += __shfl_down_sync(0xffffffffu, s.y, o);
    }
    int warp = tid >> 5, lane = tid & 31;
    if (lane == 0 && warp < 4) red[off + warp] = s;
    __syncthreads();
    if (tid == 0) {
        float2 t = red[off];
        t.x += red[off + 1].x + red[off + 2].x + red[off + 3].x;
        t.y += red[off + 1].y + red[off + 2].y + red[off + 3].y;
        red[off + 4] = t;
    }
    __syncthreads();
    return red[off + 4];
}

#define LREGION (64 * LSTRIDE + 64 * SSTRIDE)
#define SMEM_F2 (LREGION + 128 + 7 * 128 + 16)

__global__ void __launch_bounds__(256, 2)
cg_kernel(const float* __restrict__ nre, const float* __restrict__ nim,
          const float* __restrict__ theta, const float* __restrict__ bglob) {
    extern __shared__ float2 smbuf[];
    float2* Llong  = smbuf;
    float2* Lshort = Llong + 64 * LSTRIDE;
    float2* Us  = Lshort + 64 * SSTRIDE;
    float2* bv  = Us  + 128;
    float2* xv  = bv  + 128;
    float2* rv  = xv  + 128;
    float2* pv  = rv  + 128;
    float2* zv  = pv  + 128;
    float2* Apv = zv  + 128;
    float2* tv  = Apv + 128;
    float2* red = tv  + 128;

    int b = blockIdx.x, tid = threadIdx.x;
    int warp = tid >> 5, lane = tid & 31;
    int g = lane >> 2, q = lane & 3;
    int p = warp * 8 + g;
    const float* nre_b = nre + (size_t)b * NENT;
    const float* nim_b = nim + (size_t)b * NENT;

    // zero padded L region (tails read as 0)
    for (int i = tid; i < LREGION; i += 256)
        smbuf[i] = make_float2(0.f, 0.f);
    __syncthreads();

    // load L into padded pair layout
    for (int row = warp; row < 128; row += 8) {
        int base = (row * (row + 1)) >> 1;
        float2* dst = (row < 64) ? (Lshort + row * SSTRIDE)
                                 : (Llong + (127 - row) * LSTRIDE);
        for (int cc = lane; cc <= row; cc += 32)
            dst[cc] = make_float2(nre_b[base + cc], nim_b[base + cc]);
    }

    if (tid < 128) {
        float th = theta[(size_t)b * 128 + tid];
        float sn, cs;
        sincosf(th, &sn, &cs);
        Us[tid] = make_float2(cs, sn);
        float bb = bglob[(size_t)b * 128 + tid];
        bv[tid] = make_float2(bb, 0.f);
        rv[tid] = make_float2(bb, 0.f);
        xv[tid] = make_float2(0.f, 0.f);
    }
    __syncthreads();

    // cache this thread's LONG row (127-p) slice into registers
    float4 Lr4[16];
    {
        const float4* Ll4 = reinterpret_cast<const float4*>(Llong + p * LSTRIDE);
        #pragma unroll
        for (int k = 0; k < 16; k++)
            Lr4[k] = Ll4[q + 4 * k];
    }

    matvecW(tv, rv, Lshort, Lr4, p, q); __syncthreads();
    matvecU(zv, tv, Lshort, Llong, p, q); __syncthreads();
    if (tid < 128) pv[tid] = zv[tid];
    float2 rz = dot_all(rv, zv, red, 0);

    for (int it = 0; it < 20; ++it) {
        dirac(tv, pv, Us,  1.f); __syncthreads();
        dirac(Apv, tv, Us, -1.f); __syncthreads();
        float2 pAp = dot_all(pv, Apv, red, 8);
        float2 alpha = cdiv(rz, pAp);
        if (tid < 128) {
            xv[tid] = cadd(xv[tid], cmul(alpha, pv[tid]));
            rv[tid] = csub(rv[tid], cmul(alpha, Apv[tid]));
        }
        __syncthreads();
        matvecW(tv, rv, Lshort, Lr4, p, q); __syncthreads();
        matvecU(zv, tv, Lshort, Llong, p, q); __syncthreads();
        float2 rz2 = dot_all(rv, zv, red, 0);
        float2 beta = cdiv(rz2, rz);
        if (tid < 128)
            pv[tid] = cadd(zv[tid], cmul(beta, pv[tid]));
        rz = rz2;
        __syncthreads();
    }

    dirac(tv, xv, Us,  1.f); __syncthreads();
    dirac(Apv, tv, Us, -1.f); __syncthreads();
    if (tid < 128) Apv[tid] = csub(Apv[tid], bv[tid]);
    __syncthreads();
    float2 nrm = dot_all(Apv, Apv, red, 8);
    if (tid == 0) g_rn[b] = sqrtf(nrm.x);
}

__global__ void reduce_kernel(float* __restrict__ out) {
    __shared__ float sm[256];
    float s = 0.f;
    for (int i = threadIdx.x; i < NB; i += 256) s += g_rn[i];
    sm[threadIdx.x] = s;
    __syncthreads();
    for (int off = 128; off; off >>= 1) {
        if (threadIdx.x < off) sm[threadIdx.x] += sm[threadIdx.x + off];
        __syncthreads();
    }
    if (threadIdx.x == 0) out[0] = sm[0] * (1.0f / (float)NB);
}

// ncu captures launch index 3: keep 3 nops so idx3 = cg_kernel.
__global__ void nop_kernel() {}

extern "C" void kernel_launch(void* const* d_in, const int* in_sizes, int n_in,
                              void* d_out, int out_size) {
    const float* nre   = (const float*)d_in[0];
    const float* nim   = (const float*)d_in[1];
    const float* theta = (const float*)d_in[2];
    const float* bvec  = (const float*)d_in[3];
    float* out = (float*)d_out;

    size_t smem = (size_t)SMEM_F2 * sizeof(float2);
    cudaFuncSetAttribute(cg_kernel, cudaFuncAttributeMaxDynamicSharedMemorySize, (int)smem);
    nop_kernel<<<1, 32>>>();
    nop_kernel<<<1, 32>>>();
    nop_kernel<<<1, 32>>>();
    cg_kernel<<<NB, 256, smem>>>(nre, nim, theta, bvec);
    reduce_kernel<<<1, 256>>>(out);
}

// round 6
// speedup vs baseline: 1.5585x; 1.5585x over previous
#include <cuda_runtime.h>
#include <math.h>

#define NB      2048
#define NENT    8256
#define KAPPA   0.276f
#define PSTRIDE 132   // pair-block stride (f2): ==4 mod 16, even

__device__ float g_rn[NB];

__device__ __forceinline__ float2 cmul(float2 a, float2 b) {
    return make_float2(a.x * b.x - a.y * b.y, a.x * b.y + a.y * b.x);
}
__device__ __forceinline__ float2 cadd(float2 a, float2 b) {
    return make_float2(a.x + b.x, a.y + b.y);
}
__device__ __forceinline__ float2 csub(float2 a, float2 b) {
    return make_float2(a.x - b.x, a.y - b.y);
}
__device__ __forceinline__ float2 cdiv(float2 a, float2 b) {
    float inv = 1.0f / (b.x * b.x + b.y * b.y);
    return make_float2((a.x * b.x + a.y * b.y) * inv,
                       (a.y * b.x - a.x * b.y) * inv);
}

// Pair block p: long row 127-p at f2 offset 132p (len 128-p),
// short row p at 132p + (128-p) + (p&1) (len p+1). Gap (p odd) is zeroed.

// ---------- w = L * v ----------
__device__ __forceinline__ void matvecW(float2* __restrict__ wout,
                                        const float2* __restrict__ vin,
                                        const float2* __restrict__ LP,
                                        int p, int q) {
    const float2* base = LP + PSTRIDE * p;
    const float4* L4 = reinterpret_cast<const float4*>(base);
    const float4* v4 = reinterpret_cast<const float4*>(vin);
    // long row 127-p: float4 over cols; overshoot lands on zeroed gap
    float4 a4 = make_float4(0.f, 0.f, 0.f, 0.f);
    int jmax = (127 - p) >> 1;
    #pragma unroll 4
    for (int j = q; j <= jmax; j += 4) {
        float4 lf = L4[j], vf = v4[j];
        a4.x = fmaf(lf.x, vf.x, fmaf(-lf.y, vf.y, a4.x));
        a4.y = fmaf(lf.x, vf.y, fmaf( lf.y, vf.x, a4.y));
        a4.z = fmaf(lf.z, vf.z, fmaf(-lf.w, vf.w, a4.z));
        a4.w = fmaf(lf.z, vf.w, fmaf( lf.w, vf.z, a4.w));
    }
    float2 as = make_float2(a4.x + a4.z, a4.y + a4.w);
    // short row p: float2
    const float2* S = base + (128 - p) + (p & 1);
    float2 ar = make_float2(0.f, 0.f);
    #pragma unroll 2
    for (int c = q; c <= p; c += 4) {
        float2 l = S[c], v = vin[c];
        ar.x = fmaf(l.x, v.x, fmaf(-l.y, v.y, ar.x));
        ar.y = fmaf(l.x, v.y, fmaf( l.y, v.x, ar.y));
    }
    #pragma unroll
    for (int o = 1; o <= 2; o <<= 1) {
        ar.x += __shfl_xor_sync(0xffffffffu, ar.x, o);
        ar.y += __shfl_xor_sync(0xffffffffu, ar.y, o);
        as.x += __shfl_xor_sync(0xffffffffu, as.x, o);
        as.y += __shfl_xor_sync(0xffffffffu, as.y, o);
    }
    if (q == 0) { wout[p] = ar; wout[127 - p] = as; }
}

// ---------- u = L^H * w ----------
__device__ __forceinline__ void matvecU(float2* __restrict__ uout,
                                        const float2* __restrict__ win,
                                        const float2* __restrict__ LP,
                                        int c, int q) {
    int c2 = 127 - c;
    float2 ac = make_float2(0.f, 0.f), ac2 = make_float2(0.f, 0.f);
    {   // long rows (col c<=63 present in all): pair p' = q+4k, k=0..15
        const float2* Lp = LP + q * PSTRIDE + c;
        #pragma unroll 4
        for (int k = 0; k < 16; k++) {
            float2 wl = win[127 - (q + 4 * k)];
            float2 l = *Lp;
            ac.x = fmaf(l.x, wl.x, fmaf( l.y, wl.y, ac.x));
            ac.y = fmaf(l.x, wl.y, fmaf(-l.y, wl.x, ac.y));
            Lp += 4 * PSTRIDE;
        }
    }
    {   // complement column c2: long rows with p' = q..c step 4
        const float2* Lp = LP + q * PSTRIDE + c2;
        #pragma unroll 4
        for (int p = q; p <= c; p += 4) {
            float2 wl = win[127 - p];
            float2 l = *Lp;
            ac2.x = fmaf(l.x, wl.x, fmaf( l.y, wl.y, ac2.x));
            ac2.y = fmaf(l.x, wl.y, fmaf(-l.y, wl.x, ac2.y));
            Lp += 4 * PSTRIDE;
        }
    }
    {   // short rows r = c+q .. 63 step 4; addr = 131r + 128 + (r&1) + c, stride 524
        int r0 = c + q;
        const float2* Sp = LP + 131 * r0 + 128 + (r0 & 1) + c;
        #pragma unroll 4
        for (int r = r0; r <= 63; r += 4) {
            float2 ws = win[r];
            float2 l = *Sp;
            ac.x = fmaf(l.x, ws.x, fmaf( l.y, ws.y, ac.x));
            ac.y = fmaf(l.x, ws.y, fmaf(-l.y, ws.x, ac.y));
            Sp += 4 * 131;
        }
    }
    #pragma unroll
    for (int o = 1; o <= 2; o <<= 1) {
        ac.x  += __shfl_xor_sync(0xffffffffu, ac.x,  o);
        ac.y  += __shfl_xor_sync(0xffffffffu, ac.y,  o);
        ac2.x += __shfl_xor_sync(0xffffffffu, ac2.x, o);
        ac2.y += __shfl_xor_sync(0xffffffffu, ac2.y, o);
    }
    if (q == 0) { uout[c] = ac; uout[c2] = ac2; }
}

// ---------- Wilson-Dirac stencil: g=+1 -> D, g=-1 -> Ddag ----------
__device__ __forceinline__ void dirac(float2* __restrict__ out,
                                      const float2* __restrict__ in,
                                      const float2* __restrict__ Us,
                                      float g) {
    int t = threadIdx.x;
    if (t < 64) {
        int x = t >> 3, y = t & 7;
        float2 a0 = in[2 * t], a1 = in[2 * t + 1];
        float2 s0 = make_float2(0.f, 0.f), s1 = make_float2(0.f, 0.f);
        {   // mu = 0, G = sigma_x
            int sp = (((x + 1) & 7) << 3) | y;
            int sm = (((x + 7) & 7) << 3) | y;
            float2 u  = Us[t];
            float2 ub = Us[sm]; ub.y = -ub.y;
            float2 f0 = cmul(u,  in[2 * sp]), f1 = cmul(u,  in[2 * sp + 1]);
            float2 b0 = cmul(ub, in[2 * sm]), b1 = cmul(ub, in[2 * sm + 1]);
            s0.x += f0.x - g * f1.x + b0.x + g * b1.x;
            s0.y += f0.y - g * f1.y + b0.y + g * b1.y;
            s1.x += f1.x - g * f0.x + b1.x + g * b0.x;
            s1.y += f1.y - g * f0.y + b1.y + g * b0.y;
        }
        {   // mu = 1, G = sigma_y
            int sp = (x << 3) | ((y + 1) & 7);
            int sm = (x << 3) | ((y + 7) & 7);
            float2 u  = Us[64 + t];
            float2 ub = Us[64 + sm]; ub.y = -ub.y;
            float2 f0 = cmul(u,  in[2 * sp]), f1 = cmul(u,  in[2 * sp + 1]);
            float2 b0 = cmul(ub, in[2 * sm]), b1 = cmul(ub, in[2 * sm + 1]);
            s0.x += f0.x - g * f1.y + b0.x + g * b1.y;
            s0.y += f0.y + g * f1.x + b0.y - g * b1.x;
            s1.x += f1.x + g * f0.y + b1.x - g * b0.y;
            s1.y += f1.y - g * f0.x + b1.y + g * b0.x;
        }
        out[2 * t]     = make_float2(a0.x - KAPPA * s0.x, a0.y - KAPPA * s0.y);
        out[2 * t + 1] = make_float2(a1.x - KAPPA * s1.x, a1.y - KAPPA * s1.y);
    }
}

// ---------- block-wide complex dot (rotating red bank) ----------
__device__ __forceinline__ float2 dot_all(const float2* __restrict__ a,
                                          const float2* __restrict__ c,
                                          float2* __restrict__ red, int off) {
    int tid = threadIdx.x;
    float2 s = make_float2(0.f, 0.f);
    if (tid < 128) {
        float2 av = a[tid], cv = c[tid];
        s.x = av.x * cv.x + av.y * cv.y;
        s.y = av.x * cv.y - av.y * cv.x;
    }
    #pragma unroll
    for (int o = 16; o; o >>= 1) {
        s.x += __shfl_down_sync(0xffffffffu, s.x, o);
        s.y += __shfl_down_sync(0xffffffffu, s.y, o);
    }
    int warp = tid >> 5, lane = tid & 31;
    if (lane == 0 && warp < 4) red[off + warp] = s;
    __syncthreads();
    if (tid == 0) {
        float2 t = red[off];
        t.x += red[off + 1].x + red[off + 2].x + red[off + 3].x;
        t.y += red[off + 1].y + red[off + 2].y + red[off + 3].y;
        red[off + 4] = t;
    }
    __syncthreads();
    return red[off + 4];
}

#define LREGION (64 * PSTRIDE)                  // 8448 f2
#define SMEM_F2 (LREGION + 128 + 6 * 128 + 16)  // L + Us + 6 vecs + red = 9360 f2

__global__ void __launch_bounds__(256, 3)
cg_kernel(const float* __restrict__ nre, const float* __restrict__ nim,
          const float* __restrict__ theta, const float* __restrict__ bglob) {
    extern __shared__ float2 smbuf[];
    float2* LP  = smbuf;
    float2* Us  = LP  + LREGION;
    float2* xv  = Us  + 128;
    float2* rv  = xv  + 128;
    float2* pv  = rv  + 128;
    float2* zv  = pv  + 128;
    float2* Apv = zv  + 128;
    float2* tv  = Apv + 128;
    float2* red = tv  + 128;

    int b = blockIdx.x, tid = threadIdx.x;
    int warp = tid >> 5, lane = tid & 31;
    int g = lane >> 2, q = lane & 3;
    int p = warp * 8 + g;
    const float* nre_b = nre + (size_t)b * NENT;
    const float* nim_b = nim + (size_t)b * NENT;

    // zero L region (gaps must read as 0 for the float4 overshoot)
    for (int i = tid; i < LREGION; i += 256)
        LP[i] = make_float2(0.f, 0.f);
    __syncthreads();

    // load L into pair-packed layout
    for (int row = warp; row < 128; row += 8) {
        int base = (row * (row + 1)) >> 1;
        float2* dst = (row < 64)
            ? (LP + PSTRIDE * row + (128 - row) + (row & 1))   // short row
            : (LP + PSTRIDE * (127 - row));                    // long row
        for (int cc = lane; cc <= row; cc += 32)
            dst[cc] = make_float2(nre_b[base + cc], nim_b[base + cc]);
    }

    if (tid < 128) {
        float th = theta[(size_t)b * 128 + tid];
        float sn, cs;
        sincosf(th, &sn, &cs);
        Us[tid] = make_float2(cs, sn);
        float bb = bglob[(size_t)b * 128 + tid];
        rv[tid] = make_float2(bb, 0.f);
        xv[tid] = make_float2(0.f, 0.f);
    }
    __syncthreads();

    matvecW(tv, rv, LP, p, q); __syncthreads();
    matvecU(zv, tv, LP, p, q); __syncthreads();
    if (tid < 128) pv[tid] = zv[tid];
    float2 rz = dot_all(rv, zv, red, 0);

    for (int it = 0; it < 20; ++it) {
        dirac(tv, pv, Us,  1.f); __syncthreads();
        dirac(Apv, tv, Us, -1.f); __syncthreads();
        float2 pAp = dot_all(pv, Apv, red, 8);
        float2 alpha = cdiv(rz, pAp);
        if (tid < 128) {
            xv[tid] = cadd(xv[tid], cmul(alpha, pv[tid]));
            rv[tid] = csub(rv[tid], cmul(alpha, Apv[tid]));
        }
        __syncthreads();
        matvecW(tv, rv, LP, p, q); __syncthreads();
        matvecU(zv, tv, LP, p, q); __syncthreads();
        float2 rz2 = dot_all(rv, zv, red, 0);
        float2 beta = cdiv(rz2, rz);
        if (tid < 128)
            pv[tid] = cadd(zv[tid], cmul(beta, pv[tid]));
        rz = rz2;
        __syncthreads();
    }

    // residual: || A(x) - b ||  (b re-read from global)
    dirac(tv, xv, Us,  1.f); __syncthreads();
    dirac(Apv, tv, Us, -1.f); __syncthreads();
    if (tid < 128) {
        float bb = bglob[(size_t)b * 128 + tid];
        Apv[tid] = csub(Apv[tid], make_float2(bb, 0.f));
    }
    __syncthreads();
    float2 nrm = dot_all(Apv, Apv, red, 8);
    if (tid == 0) g_rn[b] = sqrtf(nrm.x);
}

__global__ void reduce_kernel(float* __restrict__ out) {
    __shared__ float sm[256];
    float s = 0.f;
    for (int i = threadIdx.x; i < NB; i += 256) s += g_rn[i];
    sm[threadIdx.x] = s;
    __syncthreads();
    for (int off = 128; off; off >>= 1) {
        if (threadIdx.x < off) sm[threadIdx.x] += sm[threadIdx.x + off];
        __syncthreads();
    }
    if (threadIdx.x == 0) out[0] = sm[0] * (1.0f / (float)NB);
}

// ncu captures launch index 3: keep 3 nops so idx3 = cg_kernel.
__global__ void nop_kernel() {}

extern "C" void kernel_launch(void* const* d_in, const int* in_sizes, int n_in,
                              void* d_out, int out_size) {
    const float* nre   = (const float*)d_in[0];
    const float* nim   = (const float*)d_in[1];
    const float* theta = (const float*)d_in[2];
    const float* bvec  = (const float*)d_in[3];
    float* out = (float*)d_out;

    size_t smem = (size_t)SMEM_F2 * sizeof(float2);   // 74,880 B -> 3 CTAs/SM
    cudaFuncSetAttribute(cg_kernel, cudaFuncAttributeMaxDynamicSharedMemorySize, (int)smem);
    nop_kernel<<<1, 32>>>();
    nop_kernel<<<1, 32>>>();
    nop_kernel<<<1, 32>>>();
    cg_kernel<<<NB, 256, smem>>>(nre, nim, theta, bvec);
    reduce_kernel<<<1, 256>>>(out);
}

// round 7
// speedup vs baseline: 1.6023x; 1.0281x over previous
#include <cuda_runtime.h>
#include <math.h>

#define NB      2048
#define NENT    8256
#define KAPPA   0.276f
#define PSTRIDE 132   // pair-block stride (f2): == 4 mod 16

__device__ float g_rn[NB];

__device__ __forceinline__ float2 cmul(float2 a, float2 b) {
    return make_float2(a.x * b.x - a.y * b.y, a.x * b.y + a.y * b.x);
}
__device__ __forceinline__ float2 cadd(float2 a, float2 b) {
    return make_float2(a.x + b.x, a.y + b.y);
}
__device__ __forceinline__ float2 csub(float2 a, float2 b) {
    return make_float2(a.x - b.x, a.y - b.y);
}
__device__ __forceinline__ float2 cdiv(float2 a, float2 b) {
    float inv = 1.0f / (b.x * b.x + b.y * b.y);
    return make_float2((a.x * b.x + a.y * b.y) * inv,
                       (a.y * b.x - a.x * b.y) * inv);
}

// Layout: block p (0..63) at f2 offset 132p:
//   long row 127-p at 132p                    (len 128-p)   start==4(p%4) mod 16 (132p does)
//   short row s(p)=4a+((b-a)&3), p=4a+b, at 132p+(128-p)+(p&3)  (len s+1)
// Both starts == 4(key%4) (mod 16) -> all four access streams bank-conflict-free.
__device__ __forceinline__ int short_row_of_block(int p) {
    int a = p >> 2, b = p & 3;
    return 4 * a + ((b - a) & 3);
}
__device__ __forceinline__ int block_of_short_row(int s) {
    int a = s >> 2, rho = s & 3;
    return 4 * a + ((a + rho) & 3);
}
__device__ __forceinline__ int short_row_offset(int p) {
    return PSTRIDE * p + (128 - p) + (p & 3);
}

// ---------- w = L * v ----------
__device__ __forceinline__ void matvecW(float2* __restrict__ wout,
                                        const float2* __restrict__ vin,
                                        const float2* __restrict__ LP,
                                        int p, int q, int s) {
    const float2* Lr = LP + PSTRIDE * p;            // long row 127-p
    float2 as = make_float2(0.f, 0.f);
    int lim = 127 - p;
    #pragma unroll 4
    for (int c = q; c <= lim; c += 4) {
        float2 l = Lr[c], v = vin[c];
        as.x = fmaf(l.x, v.x, fmaf(-l.y, v.y, as.x));
        as.y = fmaf(l.x, v.y, fmaf( l.y, v.x, as.y));
    }
    const float2* Sr = LP + short_row_offset(p);    // short row s
    float2 ar = make_float2(0.f, 0.f);
    #pragma unroll 2
    for (int c = q; c <= s; c += 4) {
        float2 l = Sr[c], v = vin[c];
        ar.x = fmaf(l.x, v.x, fmaf(-l.y, v.y, ar.x));
        ar.y = fmaf(l.x, v.y, fmaf( l.y, v.x, ar.y));
    }
    #pragma unroll
    for (int o = 1; o <= 2; o <<= 1) {
        ar.x += __shfl_xor_sync(0xffffffffu, ar.x, o);
        ar.y += __shfl_xor_sync(0xffffffffu, ar.y, o);
        as.x += __shfl_xor_sync(0xffffffffu, as.x, o);
        as.y += __shfl_xor_sync(0xffffffffu, as.y, o);
    }
    if (q == 0) { wout[s] = ar; wout[127 - p] = as; }
}

// ---------- u = L^H * w ----------
__device__ __forceinline__ void matvecU(float2* __restrict__ uout,
                                        const float2* __restrict__ win,
                                        const float2* __restrict__ LP,
                                        int c, int q) {
    int c2 = 127 - c;
    float2 ac = make_float2(0.f, 0.f), ac2 = make_float2(0.f, 0.f);
    {   // long rows (col c<=63 present in all): blocks p' = q+4k, k=0..15
        const float2* Lp = LP + q * PSTRIDE + c;
        #pragma unroll 4
        for (int k = 0; k < 16; k++) {
            float2 wl = win[127 - (q + 4 * k)];
            float2 l = *Lp;
            ac.x = fmaf(l.x, wl.x, fmaf( l.y, wl.y, ac.x));
            ac.y = fmaf(l.x, wl.y, fmaf(-l.y, wl.x, ac.y));
            Lp += 4 * PSTRIDE;
        }
    }
    {   // complement column c2 (>=64): long rows, blocks p' = q..c step 4
        const float2* Lp = LP + q * PSTRIDE + c2;
        #pragma unroll 4
        for (int p = q; p <= c; p += 4) {
            float2 wl = win[127 - p];
            float2 l = *Lp;
            ac2.x = fmaf(l.x, wl.x, fmaf( l.y, wl.y, ac2.x));
            ac2.y = fmaf(l.x, wl.y, fmaf(-l.y, wl.x, ac2.y));
            Lp += 4 * PSTRIDE;
        }
    }
    {   // short rows s = c+q .. 63 step 4 (swizzled block lookup)
        #pragma unroll 4
        for (int s = c + q; s <= 63; s += 4) {
            int p2 = block_of_short_row(s);
            float2 l = LP[short_row_offset(p2) + c];
            float2 ws = win[s];
            ac.x = fmaf(l.x, ws.x, fmaf( l.y, ws.y, ac.x));
            ac.y = fmaf(l.x, ws.y, fmaf(-l.y, ws.x, ac.y));
        }
    }
    #pragma unroll
    for (int o = 1; o <= 2; o <<= 1) {
        ac.x  += __shfl_xor_sync(0xffffffffu, ac.x,  o);
        ac.y  += __shfl_xor_sync(0xffffffffu, ac.y,  o);
        ac2.x += __shfl_xor_sync(0xffffffffu, ac2.x, o);
        ac2.y += __shfl_xor_sync(0xffffffffu, ac2.y, o);
    }
    if (q == 0) { uout[c] = ac; uout[c2] = ac2; }
}

// ---------- Wilson-Dirac stencil: g=+1 -> D, g=-1 -> Ddag ----------
__device__ __forceinline__ void dirac(float2* __restrict__ out,
                                      const float2* __restrict__ in,
                                      const float2* __restrict__ Us,
                                      float g) {
    int t = threadIdx.x;
    if (t < 64) {
        int x = t >> 3, y = t & 7;
        float2 a0 = in[2 * t], a1 = in[2 * t + 1];
        float2 s0 = make_float2(0.f, 0.f), s1 = make_float2(0.f, 0.f);
        {   // mu = 0, G = sigma_x
            int sp = (((x + 1) & 7) << 3) | y;
            int sm = (((x + 7) & 7) << 3) | y;
            float2 u  = Us[t];
            float2 ub = Us[sm]; ub.y = -ub.y;
            float2 f0 = cmul(u,  in[2 * sp]), f1 = cmul(u,  in[2 * sp + 1]);
            float2 b0 = cmul(ub, in[2 * sm]), b1 = cmul(ub, in[2 * sm + 1]);
            s0.x += f0.x - g * f1.x + b0.x + g * b1.x;
            s0.y += f0.y - g * f1.y + b0.y + g * b1.y;
            s1.x += f1.x - g * f0.x + b1.x + g * b0.x;
            s1.y += f1.y - g * f0.y + b1.y + g * b0.y;
        }
        {   // mu = 1, G = sigma_y
            int sp = (x << 3) | ((y + 1) & 7);
            int sm = (x << 3) | ((y + 7) & 7);
            float2 u  = Us[64 + t];
            float2 ub = Us[64 + sm]; ub.y = -ub.y;
            float2 f0 = cmul(u,  in[2 * sp]), f1 = cmul(u,  in[2 * sp + 1]);
            float2 b0 = cmul(ub, in[2 * sm]), b1 = cmul(ub, in[2 * sm + 1]);
            s0.x += f0.x - g * f1.y + b0.x + g * b1.y;
            s0.y += f0.y + g * f1.x + b0.y - g * b1.x;
            s1.x += f1.x + g * f0.y + b1.x - g * b0.y;
            s1.y += f1.y - g * f0.x + b1.y + g * b0.x;
        }
        out[2 * t]     = make_float2(a0.x - KAPPA * s0.x, a0.y - KAPPA * s0.y);
        out[2 * t + 1] = make_float2(a1.x - KAPPA * s1.x, a1.y - KAPPA * s1.y);
    }
}

// ---------- block-wide complex dot (rotating red bank) ----------
__device__ __forceinline__ float2 dot_all(const float2* __restrict__ a,
                                          const float2* __restrict__ c,
                                          float2* __restrict__ red, int off) {
    int tid = threadIdx.x;
    float2 s = make_float2(0.f, 0.f);
    if (tid < 128) {
        float2 av = a[tid], cv = c[tid];
        s.x = av.x * cv.x + av.y * cv.y;
        s.y = av.x * cv.y - av.y * cv.x;
    }
    #pragma unroll
    for (int o = 16; o; o >>= 1) {
        s.x += __shfl_down_sync(0xffffffffu, s.x, o);
        s.y += __shfl_down_sync(0xffffffffu, s.y, o);
    }
    int warp = tid >> 5, lane = tid & 31;
    if (lane == 0 && warp < 4) red[off + warp] = s;
    __syncthreads();
    if (tid == 0) {
        float2 t = red[off];
        t.x += red[off + 1].x + red[off + 2].x + red[off + 3].x;
        t.y += red[off + 1].y + red[off + 2].y + red[off + 3].y;
        red[off + 4] = t;
    }
    __syncthreads();
    return red[off + 4];
}

#define LREGION (64 * PSTRIDE)                  // 8448 f2
#define SMEM_F2 (LREGION + 128 + 6 * 128 + 16)  // 9360 f2 = 74,880 B

__global__ void __launch_bounds__(256, 3)
cg_kernel(const float* __restrict__ nre, const float* __restrict__ nim,
          const float* __restrict__ theta, const float* __restrict__ bglob) {
    extern __shared__ float2 smbuf[];
    float2* LP  = smbuf;
    float2* Us  = LP  + LREGION;
    float2* xv  = Us  + 128;
    float2* rv  = xv  + 128;
    float2* pv  = rv  + 128;
    float2* zv  = pv  + 128;
    float2* Apv = zv  + 128;
    float2* tv  = Apv + 128;
    float2* red = tv  + 128;

    int b = blockIdx.x, tid = threadIdx.x;
    int warp = tid >> 5, lane = tid & 31;
    int g = lane >> 2, q = lane & 3;
    int p = warp * 8 + g;
    int s = short_row_of_block(p);
    const float* nre_b = nre + (size_t)b * NENT;
    const float* nim_b = nim + (size_t)b * NENT;

    // zero L region (pads must read as 0)
    for (int i = tid; i < LREGION; i += 256)
        LP[i] = make_float2(0.f, 0.f);
    __syncthreads();

    // load L into swizzled pair-packed layout
    for (int row = warp; row < 128; row += 8) {
        int base = (row * (row + 1)) >> 1;
        int off;
        if (row >= 64) off = PSTRIDE * (127 - row);
        else           off = short_row_offset(block_of_short_row(row));
        for (int cc = lane; cc <= row; cc += 32)
            LP[off + cc] = make_float2(nre_b[base + cc], nim_b[base + cc]);
    }

    if (tid < 128) {
        float th = theta[(size_t)b * 128 + tid];
        float sn, cs;
        sincosf(th, &sn, &cs);
        Us[tid] = make_float2(cs, sn);
        float bb = bglob[(size_t)b * 128 + tid];
        rv[tid] = make_float2(bb, 0.f);
        xv[tid] = make_float2(0.f, 0.f);
    }
    __syncthreads();

    matvecW(tv, rv, LP, p, q, s); __syncthreads();
    matvecU(zv, tv, LP, p, q); __syncthreads();
    if (tid < 128) pv[tid] = zv[tid];
    float2 rz = dot_all(rv, zv, red, 0);

    for (int it = 0; it < 20; ++it) {
        dirac(tv, pv, Us,  1.f); __syncthreads();
        dirac(Apv, tv, Us, -1.f); __syncthreads();
        float2 pAp = dot_all(pv, Apv, red, 8);
        float2 alpha = cdiv(rz, pAp);
        if (tid < 128) {
            xv[tid] = cadd(xv[tid], cmul(alpha, pv[tid]));
            rv[tid] = csub(rv[tid], cmul(alpha, Apv[tid]));
        }
        __syncthreads();
        matvecW(tv, rv, LP, p, q, s); __syncthreads();
        matvecU(zv, tv, LP, p, q); __syncthreads();
        float2 rz2 = dot_all(rv, zv, red, 0);
        float2 beta = cdiv(rz2, rz);
        if (tid < 128)
            pv[tid] = cadd(zv[tid], cmul(beta, pv[tid]));
        rz = rz2;
        __syncthreads();
    }

    // residual: || A(x) - b ||
    dirac(tv, xv, Us,  1.f); __syncthreads();
    dirac(Apv, tv, Us, -1.f); __syncthreads();
    if (tid < 128) {
        float bb = bglob[(size_t)b * 128 + tid];
        Apv[tid] = csub(Apv[tid], make_float2(bb, 0.f));
    }
    __syncthreads();
    float2 nrm = dot_all(Apv, Apv, red, 8);
    if (tid == 0) g_rn[b] = sqrtf(nrm.x);
}

__global__ void reduce_kernel(float* __restrict__ out) {
    __shared__ float sm[256];
    float s = 0.f;
    for (int i = threadIdx.x; i < NB; i += 256) s += g_rn[i];
    sm[threadIdx.x] = s;
    __syncthreads();
    for (int off = 128; off; off >>= 1) {
        if (threadIdx.x < off) sm[threadIdx.x] += sm[threadIdx.x + off];
        __syncthreads();
    }
    if (threadIdx.x == 0) out[0] = sm[0] * (1.0f / (float)NB);
}

// ncu captures launch index 3: keep 3 nops so idx3 = cg_kernel.
__global__ void nop_kernel() {}

extern "C" void kernel_launch(void* const* d_in, const int* in_sizes, int n_in,
                              void* d_out, int out_size) {
    const float* nre   = (const float*)d_in[0];
    const float* nim   = (const float*)d_in[1];
    const float* theta = (const float*)d_in[2];
    const float* bvec  = (const float*)d_in[3];
    float* out = (float*)d_out;

    size_t smem = (size_t)SMEM_F2 * sizeof(float2);   // 74,880 B -> 3 CTAs/SM
    cudaFuncSetAttribute(cg_kernel, cudaFuncAttributeMaxDynamicSharedMemorySize, (int)smem);
    nop_kernel<<<1, 32>>>();
    nop_kernel<<<1, 32>>>();
    nop_kernel<<<1, 32>>>();
    cg_kernel<<<NB, 256, smem>>>(nre, nim, theta, bvec);
    reduce_kernel<<<1, 256>>>(out);
}

// round 8
// speedup vs baseline: 1.6048x; 1.0016x over previous
#include <cuda_runtime.h>
#include <math.h>

#define NB      2048
#define NENT    8256
#define KAPPA   0.276f
#define PSTRIDE 132   // pair-block stride (f2): == 4 mod 16

__device__ float g_rn[NB];

__device__ __forceinline__ float2 cmul(float2 a, float2 b) {
    return make_float2(a.x * b.x - a.y * b.y, a.x * b.y + a.y * b.x);
}
__device__ __forceinline__ float2 cadd(float2 a, float2 b) {
    return make_float2(a.x + b.x, a.y + b.y);
}
__device__ __forceinline__ float2 csub(float2 a, float2 b) {
    return make_float2(a.x - b.x, a.y - b.y);
}
__device__ __forceinline__ float2 cdiv(float2 a, float2 b) {
    float inv = 1.0f / (b.x * b.x + b.y * b.y);
    return make_float2((a.x * b.x + a.y * b.y) * inv,
                       (a.y * b.x - a.x * b.y) * inv);
}

// Layout: block p (0..63) at f2 offset 132p:
//   long row 127-p at 132p                    (len 128-p)   start==4(p%4) mod 16 (132p does)
//   short row s(p)=4a+((b-a)&3), p=4a+b, at 132p+(128-p)+(p&3)  (len s+1)
// Both starts == 4(key%4) (mod 16) -> all four access streams bank-conflict-free.
__device__ __forceinline__ int short_row_of_block(int p) {
    int a = p >> 2, b = p & 3;
    return 4 * a + ((b - a) & 3);
}
__device__ __forceinline__ int block_of_short_row(int s) {
    int a = s >> 2, rho = s & 3;
    return 4 * a + ((a + rho) & 3);
}
__device__ __forceinline__ int short_row_offset(int p) {
    return PSTRIDE * p + (128 - p) + (p & 3);
}

// ---------- w = L * v ----------
__device__ __forceinline__ void matvecW(float2* __restrict__ wout,
                                        const float2* __restrict__ vin,
                                        const float2* __restrict__ LP,
                                        int p, int q, int s) {
    const float2* Lr = LP + PSTRIDE * p;            // long row 127-p
    float2 as = make_float2(0.f, 0.f);
    int lim = 127 - p;
    #pragma unroll 4
    for (int c = q; c <= lim; c += 4) {
        float2 l = Lr[c], v = vin[c];
        as.x = fmaf(l.x, v.x, fmaf(-l.y, v.y, as.x));
        as.y = fmaf(l.x, v.y, fmaf( l.y, v.x, as.y));
    }
    const float2* Sr = LP + short_row_offset(p);    // short row s
    float2 ar = make_float2(0.f, 0.f);
    #pragma unroll 2
    for (int c = q; c <= s; c += 4) {
        float2 l = Sr[c], v = vin[c];
        ar.x = fmaf(l.x, v.x, fmaf(-l.y, v.y, ar.x));
        ar.y = fmaf(l.x, v.y, fmaf( l.y, v.x, ar.y));
    }
    #pragma unroll
    for (int o = 1; o <= 2; o <<= 1) {
        ar.x += __shfl_xor_sync(0xffffffffu, ar.x, o);
        ar.y += __shfl_xor_sync(0xffffffffu, ar.y, o);
        as.x += __shfl_xor_sync(0xffffffffu, as.x, o);
        as.y += __shfl_xor_sync(0xffffffffu, as.y, o);
    }
    if (q == 0) { wout[s] = ar; wout[127 - p] = as; }
}

// ---------- u = L^H * w ----------
__device__ __forceinline__ void matvecU(float2* __restrict__ uout,
                                        const float2* __restrict__ win,
                                        const float2* __restrict__ LP,
                                        int c, int q) {
    int c2 = 127 - c;
    float2 ac = make_float2(0.f, 0.f), ac2 = make_float2(0.f, 0.f);
    {   // long rows (col c<=63 present in all): blocks p' = q+4k, k=0..15
        const float2* Lp = LP + q * PSTRIDE + c;
        #pragma unroll 4
        for (int k = 0; k < 16; k++) {
            float2 wl = win[127 - (q + 4 * k)];
            float2 l = *Lp;
            ac.x = fmaf(l.x, wl.x, fmaf( l.y, wl.y, ac.x));
            ac.y = fmaf(l.x, wl.y, fmaf(-l.y, wl.x, ac.y));
            Lp += 4 * PSTRIDE;
        }
    }
    {   // complement column c2 (>=64): long rows, blocks p' = q..c step 4
        const float2* Lp = LP + q * PSTRIDE + c2;
        #pragma unroll 4
        for (int p = q; p <= c; p += 4) {
            float2 wl = win[127 - p];
            float2 l = *Lp;
            ac2.x = fmaf(l.x, wl.x, fmaf( l.y, wl.y, ac2.x));
            ac2.y = fmaf(l.x, wl.y, fmaf(-l.y, wl.x, ac2.y));
            Lp += 4 * PSTRIDE;
        }
    }
    {   // short rows s = c+q .. 63 step 4 (swizzled block lookup)
        #pragma unroll 4
        for (int s = c + q; s <= 63; s += 4) {
            int p2 = block_of_short_row(s);
            float2 l = LP[short_row_offset(p2) + c];
            float2 ws = win[s];
            ac.x = fmaf(l.x, ws.x, fmaf( l.y, ws.y, ac.x));
            ac.y = fmaf(l.x, ws.y, fmaf(-l.y, ws.x, ac.y));
        }
    }
    #pragma unroll
    for (int o = 1; o <= 2; o <<= 1) {
        ac.x  += __shfl_xor_sync(0xffffffffu, ac.x,  o);
        ac.y  += __shfl_xor_sync(0xffffffffu, ac.y,  o);
        ac2.x += __shfl_xor_sync(0xffffffffu, ac2.x, o);
        ac2.y += __shfl_xor_sync(0xffffffffu, ac2.y, o);
    }
    if (q == 0) { uout[c] = ac; uout[c2] = ac2; }
}

// ---------- Wilson-Dirac stencil: g=+1 -> D, g=-1 -> Ddag ----------
__device__ __forceinline__ void dirac(float2* __restrict__ out,
                                      const float2* __restrict__ in,
                                      const float2* __restrict__ Us,
                                      float g) {
    int t = threadIdx.x;
    if (t < 64) {
        int x = t >> 3, y = t & 7;
        float2 a0 = in[2 * t], a1 = in[2 * t + 1];
        float2 s0 = make_float2(0.f, 0.f), s1 = make_float2(0.f, 0.f);
        {   // mu = 0, G = sigma_x
            int sp = (((x + 1) & 7) << 3) | y;
            int sm = (((x + 7) & 7) << 3) | y;
            float2 u  = Us[t];
            float2 ub = Us[sm]; ub.y = -ub.y;
            float2 f0 = cmul(u,  in[2 * sp]), f1 = cmul(u,  in[2 * sp + 1]);
            float2 b0 = cmul(ub, in[2 * sm]), b1 = cmul(ub, in[2 * sm + 1]);
            s0.x += f0.x - g * f1.x + b0.x + g * b1.x;
            s0.y += f0.y - g * f1.y + b0.y + g * b1.y;
            s1.x += f1.x - g * f0.x + b1.x + g * b0.x;
            s1.y += f1.y - g * f0.y + b1.y + g * b0.y;
        }
        {   // mu = 1, G = sigma_y
            int sp = (x << 3) | ((y + 1) & 7);
            int sm = (x << 3) | ((y + 7) & 7);
            float2 u  = Us[64 + t];
            float2 ub = Us[64 + sm]; ub.y = -ub.y;
            float2 f0 = cmul(u,  in[2 * sp]), f1 = cmul(u,  in[2 * sp + 1]);
            float2 b0 = cmul(ub, in[2 * sm]), b1 = cmul(ub, in[2 * sm + 1]);
            s0.x += f0.x - g * f1.y + b0.x + g * b1.y;
            s0.y += f0.y + g * f1.x + b0.y - g * b1.x;
            s1.x += f1.x + g * f0.y + b1.x - g * b0.y;
            s1.y += f1.y - g * f0.x + b1.y + g * b0.x;
        }
        out[2 * t]     = make_float2(a0.x - KAPPA * s0.x, a0.y - KAPPA * s0.y);
        out[2 * t + 1] = make_float2(a1.x - KAPPA * s1.x, a1.y - KAPPA * s1.y);
    }
}

// ---------- block-wide complex dot (rotating red bank) ----------
__device__ __forceinline__ float2 dot_all(const float2* __restrict__ a,
                                          const float2* __restrict__ c,
                                          float2* __restrict__ red, int off) {
    int tid = threadIdx.x;
    float2 s = make_float2(0.f, 0.f);
    if (tid < 128) {
        float2 av = a[tid], cv = c[tid];
        s.x = av.x * cv.x + av.y * cv.y;
        s.y = av.x * cv.y - av.y * cv.x;
    }
    #pragma unroll
    for (int o = 16; o; o >>= 1) {
        s.x += __shfl_down_sync(0xffffffffu, s.x, o);
        s.y += __shfl_down_sync(0xffffffffu, s.y, o);
    }
    int warp = tid >> 5, lane = tid & 31;
    if (lane == 0 && warp < 4) red[off + warp] = s;
    __syncthreads();
    if (tid == 0) {
        float2 t = red[off];
        t.x += red[off + 1].x + red[off + 2].x + red[off + 3].x;
        t.y += red[off + 1].y + red[off + 2].y + red[off + 3].y;
        red[off + 4] = t;
    }
    __syncthreads();
    return red[off + 4];
}

#define LREGION (64 * PSTRIDE)                  // 8448 f2
#define SMEM_F2 (LREGION + 128 + 6 * 128 + 16)  // 9360 f2 = 74,880 B

__global__ void __launch_bounds__(256, 3)
cg_kernel(const float* __restrict__ nre, const float* __restrict__ nim,
          const float* __restrict__ theta, const float* __restrict__ bglob) {
    extern __shared__ float2 smbuf[];
    float2* LP  = smbuf;
    float2* Us  = LP  + LREGION;
    float2* xv  = Us  + 128;
    float2* rv  = xv  + 128;
    float2* pv  = rv  + 128;
    float2* zv  = pv  + 128;
    float2* Apv = zv  + 128;
    float2* tv  = Apv + 128;
    float2* red = tv  + 128;

    int b = blockIdx.x, tid = threadIdx.x;
    int warp = tid >> 5, lane = tid & 31;
    int g = lane >> 2, q = lane & 3;
    int p = warp * 8 + g;
    int s = short_row_of_block(p);
    const float* nre_b = nre + (size_t)b * NENT;
    const float* nim_b = nim + (size_t)b * NENT;

    // zero L region (pads must read as 0)
    for (int i = tid; i < LREGION; i += 256)
        LP[i] = make_float2(0.f, 0.f);
    __syncthreads();

    // load L into swizzled pair-packed layout
    for (int row = warp; row < 128; row += 8) {
        int base = (row * (row + 1)) >> 1;
        int off;
        if (row >= 64) off = PSTRIDE * (127 - row);
        else           off = short_row_offset(block_of_short_row(row));
        for (int cc = lane; cc <= row; cc += 32)
            LP[off + cc] = make_float2(nre_b[base + cc], nim_b[base + cc]);
    }

    if (tid < 128) {
        float th = theta[(size_t)b * 128 + tid];
        float sn, cs;
        sincosf(th, &sn, &cs);
        Us[tid] = make_float2(cs, sn);
        float bb = bglob[(size_t)b * 128 + tid];
        rv[tid] = make_float2(bb, 0.f);
        xv[tid] = make_float2(0.f, 0.f);
    }
    __syncthreads();

    matvecW(tv, rv, LP, p, q, s); __syncthreads();
    matvecU(zv, tv, LP, p, q); __syncthreads();
    if (tid < 128) pv[tid] = zv[tid];
    float2 rz = dot_all(rv, zv, red, 0);

    for (int it = 0; it < 20; ++it) {
        dirac(tv, pv, Us,  1.f); __syncthreads();
        dirac(Apv, tv, Us, -1.f); __syncthreads();
        float2 pAp = dot_all(pv, Apv, red, 8);
        float2 alpha = cdiv(rz, pAp);
        if (tid < 128) {
            xv[tid] = cadd(xv[tid], cmul(alpha, pv[tid]));
            rv[tid] = csub(rv[tid], cmul(alpha, Apv[tid]));
        }
        __syncthreads();
        matvecW(tv, rv, LP, p, q, s); __syncthreads();
        matvecU(zv, tv, LP, p, q); __syncthreads();
        float2 rz2 = dot_all(rv, zv, red, 0);
        float2 beta = cdiv(rz2, rz);
        if (tid < 128)
            pv[tid] = cadd(zv[tid], cmul(beta, pv[tid]));
        rz = rz2;
        __syncthreads();
    }

    // residual: || A(x) - b ||
    dirac(tv, xv, Us,  1.f); __syncthreads();
    dirac(Apv, tv, Us, -1.f); __syncthreads();
    if (tid < 128) {
        float bb = bglob[(size_t)b * 128 + tid];
        Apv[tid] = csub(Apv[tid], make_float2(bb, 0.f));
    }
    __syncthreads();
    float2 nrm = dot_all(Apv, Apv, red, 8);
    if (tid == 0) g_rn[b] = sqrtf(nrm.x);
}

__global__ void reduce_kernel(float* __restrict__ out) {
    __shared__ float sm[256];
    float s = 0.f;
    for (int i = threadIdx.x; i < NB; i += 256) s += g_rn[i];
    sm[threadIdx.x] = s;
    __syncthreads();
    for (int off = 128; off; off >>= 1) {
        if (threadIdx.x < off) sm[threadIdx.x] += sm[threadIdx.x + off];
        __syncthreads();
    }
    if (threadIdx.x == 0) out[0] = sm[0] * (1.0f / (float)NB);
}

// ncu captures launch index 3: keep 3 nops so idx3 = cg_kernel.
__global__ void nop_kernel() {}

extern "C" void kernel_launch(void* const* d_in, const int* in_sizes, int n_in,
                              void* d_out, int out_size) {
    const float* nre   = (const float*)d_in[0];
    const float* nim   = (const float*)d_in[1];
    const float* theta = (const float*)d_in[2];
    const float* bvec  = (const float*)d_in[3];
    float* out = (float*)d_out;

    size_t smem = (size_t)SMEM_F2 * sizeof(float2);   // 74,880 B -> 3 CTAs/SM
    cudaFuncSetAttribute(cg_kernel, cudaFuncAttributeMaxDynamicSharedMemorySize, (int)smem);
    nop_kernel<<<1, 32>>>();
    nop_kernel<<<1, 32>>>();
    nop_kernel<<<1, 32>>>();
    cg_kernel<<<NB, 256, smem>>>(nre, nim, theta, bvec);
    reduce_kernel<<<1, 256>>>(out);
}

// round 9
// speedup vs baseline: 1.6089x; 1.0026x over previous
#include <cuda_runtime.h>
#include <math.h>

#define NB      2048
#define NENT    8256
#define KAPPA   0.276f
#define PSTRIDE 132   // pair-block stride (f2): == 4 mod 16

__device__ float g_rn[NB];

__device__ __forceinline__ float2 cmul(float2 a, float2 b) {
    return make_float2(a.x * b.x - a.y * b.y, a.x * b.y + a.y * b.x);
}
__device__ __forceinline__ float2 cadd(float2 a, float2 b) {
    return make_float2(a.x + b.x, a.y + b.y);
}
__device__ __forceinline__ float2 csub(float2 a, float2 b) {
    return make_float2(a.x - b.x, a.y - b.y);
}
__device__ __forceinline__ float2 cdiv(float2 a, float2 b) {
    float inv = 1.0f / (b.x * b.x + b.y * b.y);
    return make_float2((a.x * b.x + a.y * b.y) * inv,
                       (a.y * b.x - a.x * b.y) * inv);
}

// Layout: block p (0..63) at f2 offset 132p:
//   long row 127-p at 132p                    (len 128-p)   start==4(p%4) mod 16 (132p does)
//   short row s(p)=4a+((b-a)&3), p=4a+b, at 132p+(128-p)+(p&3)  (len s+1)
// Both starts == 4(key%4) (mod 16) -> all four access streams bank-conflict-free.
__device__ __forceinline__ int short_row_of_block(int p) {
    int a = p >> 2, b = p & 3;
    return 4 * a + ((b - a) & 3);
}
__device__ __forceinline__ int block_of_short_row(int s) {
    int a = s >> 2, rho = s & 3;
    return 4 * a + ((a + rho) & 3);
}
__device__ __forceinline__ int short_row_offset(int p) {
    return PSTRIDE * p + (128 - p) + (p & 3);
}

// ---------- w = L * v ----------
__device__ __forceinline__ void matvecW(float2* __restrict__ wout,
                                        const float2* __restrict__ vin,
                                        const float2* __restrict__ LP,
                                        int p, int q, int s) {
    const float2* Lr = LP + PSTRIDE * p;            // long row 127-p
    float2 as = make_float2(0.f, 0.f);
    int lim = 127 - p;
    #pragma unroll 4
    for (int c = q; c <= lim; c += 4) {
        float2 l = Lr[c], v = vin[c];
        as.x = fmaf(l.x, v.x, fmaf(-l.y, v.y, as.x));
        as.y = fmaf(l.x, v.y, fmaf( l.y, v.x, as.y));
    }
    const float2* Sr = LP + short_row_offset(p);    // short row s
    float2 ar = make_float2(0.f, 0.f);
    #pragma unroll 2
    for (int c = q; c <= s; c += 4) {
        float2 l = Sr[c], v = vin[c];
        ar.x = fmaf(l.x, v.x, fmaf(-l.y, v.y, ar.x));
        ar.y = fmaf(l.x, v.y, fmaf( l.y, v.x, ar.y));
    }
    #pragma unroll
    for (int o = 1; o <= 2; o <<= 1) {
        ar.x += __shfl_xor_sync(0xffffffffu, ar.x, o);
        ar.y += __shfl_xor_sync(0xffffffffu, ar.y, o);
        as.x += __shfl_xor_sync(0xffffffffu, as.x, o);
        as.y += __shfl_xor_sync(0xffffffffu, as.y, o);
    }
    if (q == 0) { wout[s] = ar; wout[127 - p] = as; }
}

// ---------- u = L^H * w ----------
__device__ __forceinline__ void matvecU(float2* __restrict__ uout,
                                        const float2* __restrict__ win,
                                        const float2* __restrict__ LP,
                                        int c, int q) {
    int c2 = 127 - c;
    float2 ac = make_float2(0.f, 0.f), ac2 = make_float2(0.f, 0.f);
    {   // long rows (col c<=63 present in all): blocks p' = q+4k, k=0..15
        const float2* Lp = LP + q * PSTRIDE + c;
        #pragma unroll 4
        for (int k = 0; k < 16; k++) {
            float2 wl = win[127 - (q + 4 * k)];
            float2 l = *Lp;
            ac.x = fmaf(l.x, wl.x, fmaf( l.y, wl.y, ac.x));
            ac.y = fmaf(l.x, wl.y, fmaf(-l.y, wl.x, ac.y));
            Lp += 4 * PSTRIDE;
        }
    }
    {   // complement column c2 (>=64): long rows, blocks p' = q..c step 4
        const float2* Lp = LP + q * PSTRIDE + c2;
        #pragma unroll 4
        for (int p = q; p <= c; p += 4) {
            float2 wl = win[127 - p];
            float2 l = *Lp;
            ac2.x = fmaf(l.x, wl.x, fmaf( l.y, wl.y, ac2.x));
            ac2.y = fmaf(l.x, wl.y, fmaf(-l.y, wl.x, ac2.y));
            Lp += 4 * PSTRIDE;
        }
    }
    {   // short rows s = c+q .. 63 step 4 (swizzled block lookup)
        #pragma unroll 4
        for (int s = c + q; s <= 63; s += 4) {
            int p2 = block_of_short_row(s);
            float2 l = LP[short_row_offset(p2) + c];
            float2 ws = win[s];
            ac.x = fmaf(l.x, ws.x, fmaf( l.y, ws.y, ac.x));
            ac.y = fmaf(l.x, ws.y, fmaf(-l.y, ws.x, ac.y));
        }
    }
    #pragma unroll
    for (int o = 1; o <= 2; o <<= 1) {
        ac.x  += __shfl_xor_sync(0xffffffffu, ac.x,  o);
        ac.y  += __shfl_xor_sync(0xffffffffu, ac.y,  o);
        ac2.x += __shfl_xor_sync(0xffffffffu, ac2.x, o);
        ac2.y += __shfl_xor_sync(0xffffffffu, ac2.y, o);
    }
    if (q == 0) { uout[c] = ac; uout[c2] = ac2; }
}

// ---------- Wilson-Dirac stencil: g=+1 -> D, g=-1 -> Ddag ----------
__device__ __forceinline__ void dirac(float2* __restrict__ out,
                                      const float2* __restrict__ in,
                                      const float2* __restrict__ Us,
                                      float g) {
    int t = threadIdx.x;
    if (t < 64) {
        int x = t >> 3, y = t & 7;
        float2 a0 = in[2 * t], a1 = in[2 * t + 1];
        float2 s0 = make_float2(0.f, 0.f), s1 = make_float2(0.f, 0.f);
        {   // mu = 0, G = sigma_x
            int sp = (((x + 1) & 7) << 3) | y;
            int sm = (((x + 7) & 7) << 3) | y;
            float2 u  = Us[t];
            float2 ub = Us[sm]; ub.y = -ub.y;
            float2 f0 = cmul(u,  in[2 * sp]), f1 = cmul(u,  in[2 * sp + 1]);
            float2 b0 = cmul(ub, in[2 * sm]), b1 = cmul(ub, in[2 * sm + 1]);
            s0.x += f0.x - g * f1.x + b0.x + g * b1.x;
            s0.y += f0.y - g * f1.y + b0.y + g * b1.y;
            s1.x += f1.x - g * f0.x + b1.x + g * b0.x;
            s1.y += f1.y - g * f0.y + b1.y + g * b0.y;
        }
        {   // mu = 1, G = sigma_y
            int sp = (x << 3) | ((y + 1) & 7);
            int sm = (x << 3) | ((y + 7) & 7);
            float2 u  = Us[64 + t];
            float2 ub = Us[64 + sm]; ub.y = -ub.y;
            float2 f0 = cmul(u,  in[2 * sp]), f1 = cmul(u,  in[2 * sp + 1]);
            float2 b0 = cmul(ub, in[2 * sm]), b1 = cmul(ub, in[2 * sm + 1]);
            s0.x += f0.x - g * f1.y + b0.x + g * b1.y;
            s0.y += f0.y + g * f1.x + b0.y - g * b1.x;
            s1.x += f1.x + g * f0.y + b1.x - g * b0.y;
            s1.y += f1.y - g * f0.x + b1.y + g * b0.x;
        }
        out[2 * t]     = make_float2(a0.x - KAPPA * s0.x, a0.y - KAPPA * s0.y);
        out[2 * t + 1] = make_float2(a1.x - KAPPA * s1.x, a1.y - KAPPA * s1.y);
    }
}

// ---------- block-wide complex dot (rotating red bank) ----------
__device__ __forceinline__ float2 dot_all(const float2* __restrict__ a,
                                          const float2* __restrict__ c,
                                          float2* __restrict__ red, int off) {
    int tid = threadIdx.x;
    float2 s = make_float2(0.f, 0.f);
    if (tid < 128) {
        float2 av = a[tid], cv = c[tid];
        s.x = av.x * cv.x + av.y * cv.y;
        s.y = av.x * cv.y - av.y * cv.x;
    }
    #pragma unroll
    for (int o = 16; o; o >>= 1) {
        s.x += __shfl_down_sync(0xffffffffu, s.x, o);
        s.y += __shfl_down_sync(0xffffffffu, s.y, o);
    }
    int warp = tid >> 5, lane = tid & 31;
    if (lane == 0 && warp < 4) red[off + warp] = s;
    __syncthreads();
    if (tid == 0) {
        float2 t = red[off];
        t.x += red[off + 1].x + red[off + 2].x + red[off + 3].x;
        t.y += red[off + 1].y + red[off + 2].y + red[off + 3].y;
        red[off + 4] = t;
    }
    __syncthreads();
    return red[off + 4];
}

#define LREGION (64 * PSTRIDE)                  // 8448 f2
#define SMEM_F2 (LREGION + 128 + 6 * 128 + 16)  // 9360 f2 = 74,880 B

__global__ void __launch_bounds__(256, 3)
cg_kernel(const float* __restrict__ nre, const float* __restrict__ nim,
          const float* __restrict__ theta, const float* __restrict__ bglob) {
    extern __shared__ float2 smbuf[];
    float2* LP  = smbuf;
    float2* Us  = LP  + LREGION;
    float2* xv  = Us  + 128;
    float2* rv  = xv  + 128;
    float2* pv  = rv  + 128;
    float2* zv  = pv  + 128;
    float2* Apv = zv  + 128;
    float2* tv  = Apv + 128;
    float2* red = tv  + 128;

    int b = blockIdx.x, tid = threadIdx.x;
    int warp = tid >> 5, lane = tid & 31;
    int g = lane >> 2, q = lane & 3;
    int p = warp * 8 + g;
    int s = short_row_of_block(p);
    const float* nre_b = nre + (size_t)b * NENT;
    const float* nim_b = nim + (size_t)b * NENT;

    // zero L region (pads must read as 0)
    for (int i = tid; i < LREGION; i += 256)
        LP[i] = make_float2(0.f, 0.f);
    __syncthreads();

    // load L into swizzled pair-packed layout
    for (int row = warp; row < 128; row += 8) {
        int base = (row * (row + 1)) >> 1;
        int off;
        if (row >= 64) off = PSTRIDE * (127 - row);
        else           off = short_row_offset(block_of_short_row(row));
        for (int cc = lane; cc <= row; cc += 32)
            LP[off + cc] = make_float2(nre_b[base + cc], nim_b[base + cc]);
    }

    if (tid < 128) {
        float th = theta[(size_t)b * 128 + tid];
        float sn, cs;
        sincosf(th, &sn, &cs);
        Us[tid] = make_float2(cs, sn);
        float bb = bglob[(size_t)b * 128 + tid];
        rv[tid] = make_float2(bb, 0.f);
        xv[tid] = make_float2(0.f, 0.f);
    }
    __syncthreads();

    matvecW(tv, rv, LP, p, q, s); __syncthreads();
    matvecU(zv, tv, LP, p, q); __syncthreads();
    if (tid < 128) pv[tid] = zv[tid];
    float2 rz = dot_all(rv, zv, red, 0);

    for (int it = 0; it < 20; ++it) {
        dirac(tv, pv, Us,  1.f); __syncthreads();
        dirac(Apv, tv, Us, -1.f); __syncthreads();
        float2 pAp = dot_all(pv, Apv, red, 8);
        float2 alpha = cdiv(rz, pAp);
        if (tid < 128) {
            xv[tid] = cadd(xv[tid], cmul(alpha, pv[tid]));
            rv[tid] = csub(rv[tid], cmul(alpha, Apv[tid]));
        }
        __syncthreads();
        matvecW(tv, rv, LP, p, q, s); __syncthreads();
        matvecU(zv, tv, LP, p, q); __syncthreads();
        float2 rz2 = dot_all(rv, zv, red, 0);
        float2 beta = cdiv(rz2, rz);
        if (tid < 128)
            pv[tid] = cadd(zv[tid], cmul(beta, pv[tid]));
        rz = rz2;
        __syncthreads();
    }

    // residual: || A(x) - b ||
    dirac(tv, xv, Us,  1.f); __syncthreads();
    dirac(Apv, tv, Us, -1.f); __syncthreads();
    if (tid < 128) {
        float bb = bglob[(size_t)b * 128 + tid];
        Apv[tid] = csub(Apv[tid], make_float2(bb, 0.f));
    }
    __syncthreads();
    float2 nrm = dot_all(Apv, Apv, red, 8);
    if (tid == 0) g_rn[b] = sqrtf(nrm.x);
}

__global__ void reduce_kernel(float* __restrict__ out) {
    __shared__ float sm[256];
    float s = 0.f;
    for (int i = threadIdx.x; i < NB; i += 256) s += g_rn[i];
    sm[threadIdx.x] = s;
    __syncthreads();
    for (int off = 128; off; off >>= 1) {
        if (threadIdx.x < off) sm[threadIdx.x] += sm[threadIdx.x + off];
        __syncthreads();
    }
    if (threadIdx.x == 0) out[0] = sm[0] * (1.0f / (float)NB);
}

// ncu captures launch index 3: keep 3 nops so idx3 = cg_kernel.
__global__ void nop_kernel() {}

extern "C" void kernel_launch(void* const* d_in, const int* in_sizes, int n_in,
                              void* d_out, int out_size) {
    const float* nre   = (const float*)d_in[0];
    const float* nim   = (const float*)d_in[1];
    const float* theta = (const float*)d_in[2];
    const float* bvec  = (const float*)d_in[3];
    float* out = (float*)d_out;

    size_t smem = (size_t)SMEM_F2 * sizeof(float2);   // 74,880 B -> 3 CTAs/SM
    cudaFuncSetAttribute(cg_kernel, cudaFuncAttributeMaxDynamicSharedMemorySize, (int)smem);
    nop_kernel<<<1, 32>>>();
    nop_kernel<<<1, 32>>>();
    nop_kernel<<<1, 32>>>();
    cg_kernel<<<NB, 256, smem>>>(nre, nim, theta, bvec);
    reduce_kernel<<<1, 256>>>(out);
}